// round 7
// baseline (speedup 1.0000x reference)
#include <cuda_runtime.h>
#include <cstdint>

#define HEADS 4
#define CB    8192
#define D     64
#define M     8192            // B*N
#define DIM   256             // HEADS*D
#define QSIZE (M*DIM)
#define TM 64                 // queries per block
#define TN 128                // codes per tile
#define NTILES (CB/TN)        // 64
#define NTHREADS 128          // 16 tx * 8 ty

// dynamic smem layout:
//   Xdup: [64 k][64 r] u64 (dup'd x)     32768 B
//   Et:   [64 k][128 c] f32 (k-major)    32768 B
//   y2s:  [128] f32                        512 B
//   inds: [64] int                         256 B
#define SM_XD_BYTES  (D * TM * 8)
#define SM_ET_OFF    SM_XD_BYTES
#define SM_ET_BYTES  (D * TN * 4)
#define SM_Y2_OFF    (SM_ET_OFF + SM_ET_BYTES)
#define SM_INDS_OFF  (SM_Y2_OFF + TN * 4)
#define SMEM_BYTES   (SM_INDS_OFF + TM * 4)

__device__ float g_y2[HEADS * CB];

// ---------------------------------------------------------------------------
__global__ void vq_y2_kernel(const float* __restrict__ embed) {
    int gw   = (blockIdx.x * blockDim.x + threadIdx.x) >> 5;
    int lane = threadIdx.x & 31;
    if (gw >= HEADS * CB) return;
    float2 v = reinterpret_cast<const float2*>(embed + (size_t)gw * D)[lane];
    float s = fmaf(v.x, v.x, v.y * v.y);
    #pragma unroll
    for (int o = 16; o; o >>= 1) s += __shfl_xor_sync(0xffffffffu, s, o);
    if (lane == 0) g_y2[gw] = s;
}

// full-rate packed fp32 FMA (ptxas never emits this from C++)
__device__ __forceinline__ void ffma2(unsigned long long& acc,
                                      unsigned long long a,
                                      unsigned long long b) {
    asm("fma.rn.f32x2 %0, %1, %2, %0;" : "+l"(acc) : "l"(a), "l"(b));
}

__device__ __forceinline__ unsigned long long dup2(float v) {
    unsigned u = __float_as_uint(v);
    return ((unsigned long long)u << 32) | u;
}

__device__ __forceinline__ void upd(float sc, int cg, float& m, int& id) {
    if (sc > m) { m = sc; id = cg; }
}

// ---------------------------------------------------------------------------
// grid=(M/64, HEADS), block=128.  Fragment: 8 queries x 8 codes per thread.
// acc[i][jp] packs scores of codes (8tx+2jp, 8tx+2jp+1) for query row 8ty+i.
// score(c) = x.e_c - 0.5*|e_c|^2  (argmax-equivalent to -sqrt distance)
// ---------------------------------------------------------------------------
__global__ __launch_bounds__(NTHREADS, 3)
void vq_main_kernel(const float* __restrict__ x, const float* __restrict__ embed,
                    float* __restrict__ out, int out_size) {
    extern __shared__ char smem[];
    unsigned long long* Xd = reinterpret_cast<unsigned long long*>(smem);
    float* Et   = reinterpret_cast<float*>(smem + SM_ET_OFF);
    float* y2s  = reinterpret_cast<float*>(smem + SM_Y2_OFF);
    int*   inds = reinterpret_cast<int*>(smem + SM_INDS_OFF);

    const int h  = blockIdx.y;
    const int m0 = blockIdx.x * TM;
    const int t  = threadIdx.x;
    const int tx = t & 15;
    const int ty = t >> 4;

    const float* ebase = embed + (size_t)h * CB * D;
    const float* y2b   = g_y2 + h * CB;

    // ---- fill Xdup once: Xd[k][r] = (x,x) ----
    #pragma unroll
    for (int s = 0; s < 8; s++) {
        int slot = t + s * NTHREADS;
        int r = slot & 63, kq = slot >> 6;         // kq in 0..15
        float4 f = *reinterpret_cast<const float4*>(
            x + (size_t)(m0 + r) * DIM + h * D + kq * 4);
        Xd[(4 * kq + 0) * TM + r] = dup2(f.x);
        Xd[(4 * kq + 1) * TM + r] = dup2(f.y);
        Xd[(4 * kq + 2) * TM + r] = dup2(f.z);
        Xd[(4 * kq + 3) * TM + r] = dup2(f.w);
    }

    float rmax[8];
    int   ridx[8];
    #pragma unroll
    for (int i = 0; i < 8; i++) { rmax[i] = -3.4e38f; ridx[i] = 0; }

    const ulonglong2* XdU2 = reinterpret_cast<const ulonglong2*>(Xd);
    const ulonglong2* EtU2 = reinterpret_cast<const ulonglong2*>(Et);

    for (int tile = 0; tile < NTILES; tile++) {
        const int n0 = tile * TN;
        __syncthreads();     // prior tile done reading Et (also publishes Xd on iter 0)
        // ---- fill Et k-major: each thread owns column c = t (0..127) ----
        {
            const int c = t;
            #pragma unroll
            for (int kq = 0; kq < 16; kq++) {
                float4 f = *reinterpret_cast<const float4*>(
                    ebase + (size_t)(n0 + c) * D + kq * 4);
                Et[(4 * kq + 0) * TN + c] = f.x;
                Et[(4 * kq + 1) * TN + c] = f.y;
                Et[(4 * kq + 2) * TN + c] = f.z;
                Et[(4 * kq + 3) * TN + c] = f.w;
            }
            y2s[c] = y2b[n0 + c];
        }
        __syncthreads();

        // ---- 8x8 fragment over K=64 ----
        unsigned long long acc[8][4];
        #pragma unroll
        for (int i = 0; i < 8; i++)
            #pragma unroll
            for (int jp = 0; jp < 4; jp++) acc[i][jp] = 0ull;

        #pragma unroll 4
        for (int k = 0; k < D; k++) {
            // X: 4 broadcast LDS.128 (rows 8ty..8ty+7, dup'd).  Row = 32 ull2.
            ulonglong2 xv0 = XdU2[k * 32 + 4 * ty + 0];
            ulonglong2 xv1 = XdU2[k * 32 + 4 * ty + 1];
            ulonglong2 xv2 = XdU2[k * 32 + 4 * ty + 2];
            ulonglong2 xv3 = XdU2[k * 32 + 4 * ty + 3];
            // E: 2 LDS.128 -> natural code pairs (8tx..8tx+7).  Row = 32 ull2.
            ulonglong2 e0 = EtU2[k * 32 + 2 * tx + 0];
            ulonglong2 e1 = EtU2[k * 32 + 2 * tx + 1];

            ffma2(acc[0][0], xv0.x, e0.x); ffma2(acc[0][1], xv0.x, e0.y);
            ffma2(acc[0][2], xv0.x, e1.x); ffma2(acc[0][3], xv0.x, e1.y);
            ffma2(acc[1][0], xv0.y, e0.x); ffma2(acc[1][1], xv0.y, e0.y);
            ffma2(acc[1][2], xv0.y, e1.x); ffma2(acc[1][3], xv0.y, e1.y);
            ffma2(acc[2][0], xv1.x, e0.x); ffma2(acc[2][1], xv1.x, e0.y);
            ffma2(acc[2][2], xv1.x, e1.x); ffma2(acc[2][3], xv1.x, e1.y);
            ffma2(acc[3][0], xv1.y, e0.x); ffma2(acc[3][1], xv1.y, e0.y);
            ffma2(acc[3][2], xv1.y, e1.x); ffma2(acc[3][3], xv1.y, e1.y);
            ffma2(acc[4][0], xv2.x, e0.x); ffma2(acc[4][1], xv2.x, e0.y);
            ffma2(acc[4][2], xv2.x, e1.x); ffma2(acc[4][3], xv2.x, e1.y);
            ffma2(acc[5][0], xv2.y, e0.x); ffma2(acc[5][1], xv2.y, e0.y);
            ffma2(acc[5][2], xv2.y, e1.x); ffma2(acc[5][3], xv2.y, e1.y);
            ffma2(acc[6][0], xv3.x, e0.x); ffma2(acc[6][1], xv3.x, e0.y);
            ffma2(acc[6][2], xv3.x, e1.x); ffma2(acc[6][3], xv3.x, e1.y);
            ffma2(acc[7][0], xv3.y, e0.x); ffma2(acc[7][1], xv3.y, e0.y);
            ffma2(acc[7][2], xv3.y, e1.x); ffma2(acc[7][3], xv3.y, e1.y);
        }

        // ---- running argmax, codes scanned ascending (first-index ties) ----
        float4 yA = reinterpret_cast<const float4*>(y2s)[2 * tx];
        float4 yB = reinterpret_cast<const float4*>(y2s)[2 * tx + 1];
        const int cg = n0 + 8 * tx;
        #pragma unroll
        for (int i = 0; i < 8; i++) {
            unsigned long long a;
            a = acc[i][0];
            upd(__uint_as_float((unsigned)a)         - 0.5f * yA.x, cg + 0, rmax[i], ridx[i]);
            upd(__uint_as_float((unsigned)(a >> 32)) - 0.5f * yA.y, cg + 1, rmax[i], ridx[i]);
            a = acc[i][1];
            upd(__uint_as_float((unsigned)a)         - 0.5f * yA.z, cg + 2, rmax[i], ridx[i]);
            upd(__uint_as_float((unsigned)(a >> 32)) - 0.5f * yA.w, cg + 3, rmax[i], ridx[i]);
            a = acc[i][2];
            upd(__uint_as_float((unsigned)a)         - 0.5f * yB.x, cg + 4, rmax[i], ridx[i]);
            upd(__uint_as_float((unsigned)(a >> 32)) - 0.5f * yB.y, cg + 5, rmax[i], ridx[i]);
            a = acc[i][3];
            upd(__uint_as_float((unsigned)a)         - 0.5f * yB.z, cg + 6, rmax[i], ridx[i]);
            upd(__uint_as_float((unsigned)(a >> 32)) - 0.5f * yB.w, cg + 7, rmax[i], ridx[i]);
        }
    }

    // ---- reduce over 16 tx lanes (stays within each half-warp) ----
    #pragma unroll
    for (int i = 0; i < 8; i++) {
        float v = rmax[i];
        int  id = ridx[i];
        #pragma unroll
        for (int o = 8; o; o >>= 1) {
            float ov = __shfl_xor_sync(0xffffffffu, v, o);
            int   oi = __shfl_xor_sync(0xffffffffu, id, o);
            if (ov > v || (ov == v && oi < id)) { v = ov; id = oi; }
        }
        if (tx == 0) inds[8 * ty + i] = id;
    }
    __syncthreads();

    // ---- indices output (float, layout b n h) ----
    if (out_size >= QSIZE + M * HEADS && t < TM)
        out[QSIZE + (size_t)(m0 + t) * HEADS + h] = (float)inds[t];

    // ---- gather quantized codes (layout b n (h d)) ----
    #pragma unroll
    for (int s = 0; s < 8; s++) {
        int slot = t + s * NTHREADS;
        int r = slot >> 4, kq = slot & 15;
        int id = inds[r];
        float4 v = *reinterpret_cast<const float4*>(ebase + (size_t)id * D + kq * 4);
        *reinterpret_cast<float4*>(out + (size_t)(m0 + r) * DIM + h * D + kq * 4) = v;
    }
}

extern "C" void kernel_launch(void* const* d_in, const int* in_sizes, int n_in,
                              void* d_out, int out_size) {
    const float* x     = (const float*)d_in[0];   // [4,2048,256]
    const float* embed = (const float*)d_in[1];   // [4,8192,64]
    float* out = (float*)d_out;

    cudaFuncSetAttribute(vq_main_kernel,
                         cudaFuncAttributeMaxDynamicSharedMemorySize, SMEM_BYTES);

    vq_y2_kernel<<<(HEADS * CB) / 8, 256>>>(embed);

    dim3 grid(M / TM, HEADS);
    vq_main_kernel<<<grid, NTHREADS, SMEM_BYTES>>>(x, embed, out, out_size);
}

// round 9
// speedup vs baseline: 1.0532x; 1.0532x over previous
#include <cuda_runtime.h>
#include <cstdint>

#define HEADS 4
#define CB    8192
#define D     64
#define M     8192            // B*N
#define DIM   256             // HEADS*D
#define QSIZE (M*DIM)
#define TM 64                 // queries per block
#define TN 128                // codes per tile
#define NTILES (CB/TN)        // 64
#define NTHREADS 128          // 16 tx * 8 ty

// dynamic smem:
//   Xs:  [64 k][64 r]  f32 (undup'd, k-major)   16384 B
//   Et:  [64 k][128 c] f32 (k-major)            32768 B
//   y2s: [128] f32, inds: [64] int
#define SM_XS_BYTES  (D * TM * 4)
#define SM_ET_OFF    SM_XS_BYTES
#define SM_ET_BYTES  (D * TN * 4)
#define SM_Y2_OFF    (SM_ET_OFF + SM_ET_BYTES)
#define SM_INDS_OFF  (SM_Y2_OFF + TN * 4)
#define SMEM_BYTES   (SM_INDS_OFF + TM * 4)

__device__ float g_y2[HEADS * CB];

// ---------------------------------------------------------------------------
__global__ void vq_y2_kernel(const float* __restrict__ embed) {
    int gw   = (blockIdx.x * blockDim.x + threadIdx.x) >> 5;
    int lane = threadIdx.x & 31;
    if (gw >= HEADS * CB) return;
    float2 v = reinterpret_cast<const float2*>(embed + (size_t)gw * D)[lane];
    float s = fmaf(v.x, v.x, v.y * v.y);
    #pragma unroll
    for (int o = 16; o; o >>= 1) s += __shfl_xor_sync(0xffffffffu, s, o);
    if (lane == 0) g_y2[gw] = s;
}

// full-rate packed fp32 FMA (only reachable via PTX)
__device__ __forceinline__ void ffma2(unsigned long long& acc,
                                      unsigned long long a,
                                      unsigned long long b) {
    asm("fma.rn.f32x2 %0, %1, %2, %0;" : "+l"(acc) : "l"(a), "l"(b));
}

// (v, v) packed into one 64-bit reg pair — ALU MOVs, no smem bytes
__device__ __forceinline__ unsigned long long dupf(float v) {
    unsigned long long r;
    asm("mov.b64 %0, {%1, %1};" : "=l"(r) : "f"(v));
    return r;
}

__device__ __forceinline__ void upd(float sc, int cg, float& m, int& id) {
    if (sc > m) { m = sc; id = cg; }
}

// ---------------------------------------------------------------------------
// grid=(M/64, HEADS), block=128 (tx = t&15 codes, ty = t>>4 queries).
// Fragment: 8 queries x 8 codes / thread; acc packs adjacent code pairs.
// score(c) = x.e_c - 0.5*|e_c|^2  (argmax-equivalent to -sqrt distance)
// ---------------------------------------------------------------------------
__global__ __launch_bounds__(NTHREADS, 3)
void vq_main_kernel(const float* __restrict__ x, const float* __restrict__ embed,
                    float* __restrict__ out, int out_size) {
    extern __shared__ char smem[];
    float* Xs   = reinterpret_cast<float*>(smem);
    float* Et   = reinterpret_cast<float*>(smem + SM_ET_OFF);
    float* y2s  = reinterpret_cast<float*>(smem + SM_Y2_OFF);
    int*   inds = reinterpret_cast<int*>(smem + SM_INDS_OFF);

    const int h  = blockIdx.y;
    const int m0 = blockIdx.x * TM;
    const int t  = threadIdx.x;
    const int tx = t & 15;
    const int ty = t >> 4;

    const float* ebase = embed + (size_t)h * CB * D;
    const float* y2b   = g_y2 + h * CB;

    // ---- fill Xs once: Xs[k][r] = x[m0+r][h*64+k] (undup'd, k-major) ----
    #pragma unroll
    for (int s = 0; s < 4; s++) {
        int slot = t + s * NTHREADS;
        int r = slot & 63, kq = slot >> 6;         // kq in 0..7
        #pragma unroll
        for (int half = 0; half < 2; half++) {
            int kq8 = kq * 2 + half;               // 0..15
            float4 f = *reinterpret_cast<const float4*>(
                x + (size_t)(m0 + r) * DIM + h * D + kq8 * 4);
            Xs[(4 * kq8 + 0) * TM + r] = f.x;
            Xs[(4 * kq8 + 1) * TM + r] = f.y;
            Xs[(4 * kq8 + 2) * TM + r] = f.z;
            Xs[(4 * kq8 + 3) * TM + r] = f.w;
        }
    }

    float rmax[8];
    int   ridx[8];
    #pragma unroll
    for (int i = 0; i < 8; i++) { rmax[i] = -3.4e38f; ridx[i] = 0; }

    const float4* XsF4 = reinterpret_cast<const float4*>(Xs);   // 16 float4 per k-row
    const float4* EtF4 = reinterpret_cast<const float4*>(Et);   // 32 float4 per k-row

    for (int tile = 0; tile < NTILES; tile++) {
        const int n0 = tile * TN;
        __syncthreads();     // prior tile done reading Et (publishes Xs on iter 0)
        // ---- fill Et k-major: thread owns column c = t (0..127) ----
        {
            const int c = t;
            #pragma unroll
            for (int kq = 0; kq < 16; kq++) {
                float4 f = *reinterpret_cast<const float4*>(
                    ebase + (size_t)(n0 + c) * D + kq * 4);
                Et[(4 * kq + 0) * TN + c] = f.x;
                Et[(4 * kq + 1) * TN + c] = f.y;
                Et[(4 * kq + 2) * TN + c] = f.z;
                Et[(4 * kq + 3) * TN + c] = f.w;
            }
            y2s[c] = y2b[n0 + c];
        }
        __syncthreads();

        unsigned long long acc[8][4];
        #pragma unroll
        for (int i = 0; i < 8; i++)
            #pragma unroll
            for (int jp = 0; jp < 4; jp++) acc[i][jp] = 0ull;

        #pragma unroll 2
        for (int k = 0; k < D; k++) {
            // X: 2 LDS.128 undup'd (queries 8ty..8ty+7)
            float4 xa = XsF4[k * 16 + 2 * ty + 0];
            float4 xb = XsF4[k * 16 + 2 * ty + 1];
            // E: 2 LDS.128 -> natural code pairs (8tx..8tx+7)
            float4 ea = EtF4[k * 32 + 2 * tx + 0];
            float4 eb = EtF4[k * 32 + 2 * tx + 1];
            ulonglong2 e0 = *reinterpret_cast<ulonglong2*>(&ea);
            ulonglong2 e1 = *reinterpret_cast<ulonglong2*>(&eb);

            unsigned long long x0 = dupf(xa.x), x1 = dupf(xa.y);
            unsigned long long x2 = dupf(xa.z), x3 = dupf(xa.w);
            unsigned long long x4 = dupf(xb.x), x5 = dupf(xb.y);
            unsigned long long x6 = dupf(xb.z), x7 = dupf(xb.w);

            ffma2(acc[0][0], x0, e0.x); ffma2(acc[0][1], x0, e0.y);
            ffma2(acc[0][2], x0, e1.x); ffma2(acc[0][3], x0, e1.y);
            ffma2(acc[1][0], x1, e0.x); ffma2(acc[1][1], x1, e0.y);
            ffma2(acc[1][2], x1, e1.x); ffma2(acc[1][3], x1, e1.y);
            ffma2(acc[2][0], x2, e0.x); ffma2(acc[2][1], x2, e0.y);
            ffma2(acc[2][2], x2, e1.x); ffma2(acc[2][3], x2, e1.y);
            ffma2(acc[3][0], x3, e0.x); ffma2(acc[3][1], x3, e0.y);
            ffma2(acc[3][2], x3, e1.x); ffma2(acc[3][3], x3, e1.y);
            ffma2(acc[4][0], x4, e0.x); ffma2(acc[4][1], x4, e0.y);
            ffma2(acc[4][2], x4, e1.x); ffma2(acc[4][3], x4, e1.y);
            ffma2(acc[5][0], x5, e0.x); ffma2(acc[5][1], x5, e0.y);
            ffma2(acc[5][2], x5, e1.x); ffma2(acc[5][3], x5, e1.y);
            ffma2(acc[6][0], x6, e0.x); ffma2(acc[6][1], x6, e0.y);
            ffma2(acc[6][2], x6, e1.x); ffma2(acc[6][3], x6, e1.y);
            ffma2(acc[7][0], x7, e0.x); ffma2(acc[7][1], x7, e0.y);
            ffma2(acc[7][2], x7, e1.x); ffma2(acc[7][3], x7, e1.y);
        }

        // ---- running argmax, codes ascending (first-index tie-break) ----
        float4 yA = reinterpret_cast<const float4*>(y2s)[2 * tx];
        float4 yB = reinterpret_cast<const float4*>(y2s)[2 * tx + 1];
        const int cg = n0 + 8 * tx;
        #pragma unroll
        for (int i = 0; i < 8; i++) {
            unsigned long long a;
            a = acc[i][0];
            upd(__uint_as_float((unsigned)a)         - 0.5f * yA.x, cg + 0, rmax[i], ridx[i]);
            upd(__uint_as_float((unsigned)(a >> 32)) - 0.5f * yA.y, cg + 1, rmax[i], ridx[i]);
            a = acc[i][1];
            upd(__uint_as_float((unsigned)a)         - 0.5f * yA.z, cg + 2, rmax[i], ridx[i]);
            upd(__uint_as_float((unsigned)(a >> 32)) - 0.5f * yA.w, cg + 3, rmax[i], ridx[i]);
            a = acc[i][2];
            upd(__uint_as_float((unsigned)a)         - 0.5f * yB.x, cg + 4, rmax[i], ridx[i]);
            upd(__uint_as_float((unsigned)(a >> 32)) - 0.5f * yB.y, cg + 5, rmax[i], ridx[i]);
            a = acc[i][3];
            upd(__uint_as_float((unsigned)a)         - 0.5f * yB.z, cg + 6, rmax[i], ridx[i]);
            upd(__uint_as_float((unsigned)(a >> 32)) - 0.5f * yB.w, cg + 7, rmax[i], ridx[i]);
        }
    }

    // ---- reduce over 16 tx lanes (within half-warp) ----
    #pragma unroll
    for (int i = 0; i < 8; i++) {
        float v = rmax[i];
        int  id = ridx[i];
        #pragma unroll
        for (int o = 8; o; o >>= 1) {
            float ov = __shfl_xor_sync(0xffffffffu, v, o);
            int   oi = __shfl_xor_sync(0xffffffffu, id, o);
            if (ov > v || (ov == v && oi < id)) { v = ov; id = oi; }
        }
        if (tx == 0) inds[8 * ty + i] = id;
    }
    __syncthreads();

    // ---- indices output (float, layout b n h) ----
    if (out_size >= QSIZE + M * HEADS && t < TM)
        out[QSIZE + (size_t)(m0 + t) * HEADS + h] = (float)inds[t];

    // ---- gather quantized codes (layout b n (h d)) ----
    #pragma unroll
    for (int s = 0; s < 8; s++) {
        int slot = t + s * NTHREADS;
        int r = slot >> 4, kq = slot & 15;
        int id = inds[r];
        float4 v = *reinterpret_cast<const float4*>(ebase + (size_t)id * D + kq * 4);
        *reinterpret_cast<float4*>(out + (size_t)(m0 + r) * DIM + h * D + kq * 4) = v;
    }
}

extern "C" void kernel_launch(void* const* d_in, const int* in_sizes, int n_in,
                              void* d_out, int out_size) {
    const float* x     = (const float*)d_in[0];   // [4,2048,256]
    const float* embed = (const float*)d_in[1];   // [4,8192,64]
    float* out = (float*)d_out;

    cudaFuncSetAttribute(vq_main_kernel,
                         cudaFuncAttributeMaxDynamicSharedMemorySize, SMEM_BYTES);

    vq_y2_kernel<<<(HEADS * CB) / 8, 256>>>(embed);

    dim3 grid(M / TM, HEADS);
    vq_main_kernel<<<grid, NTHREADS, SMEM_BYTES>>>(x, embed, out, out_size);
}